// round 10
// baseline (speedup 1.0000x reference)
#include <cuda_runtime.h>

#define S_LEN 256
#define GN 8                   // interpolation grid nodes
#define THREADS 32             // one warp = one batch per block
#define RSTRIDE 68             // floats per quarter-region (64 + 4 pad)

__device__ __forceinline__ float ex2f(float v) {
    float y;
    asm("ex2.approx.ftz.f32 %0, %1;" : "=f"(y) : "f"(v));
    return y;
}

__global__ void __launch_bounds__(THREADS)
pico_transformer_adder_kernel(
    const float* __restrict__ x,
    const float* __restrict__ emb_w,
    const float* __restrict__ emb_b,
    const float* __restrict__ q_w,
    const float* __restrict__ q_b,
    const float* __restrict__ k_w,
    const float* __restrict__ k_b,
    const float* __restrict__ v_w,
    const float* __restrict__ v_b,
    const float* __restrict__ f1_w,
    const float* __restrict__ f1_b,
    const float* __restrict__ f2_w,
    const float* __restrict__ f2_b,
    float* __restrict__ out)
{
    __shared__ __align__(16) float xw[4 * RSTRIDE];   // x values only (no x^2 slab)

    const int lane = threadIdx.x;
    const int b    = blockIdx.x;

    // ---- load this batch's 8 x values per lane (coalesced 1KB) ----
    const float4* xr4 = (const float4*)(x + b * S_LEN);
    const float4 va = xr4[lane * 2];
    const float4 vb = xr4[lane * 2 + 1];

    // ---- stage x into slab: quarter r = lane>>3 at r*RSTRIDE ----
    const int base = (lane >> 3) * RSTRIDE + (lane & 7) * 8;
    *(float4*)(xw + base)     = va;
    *(float4*)(xw + base + 4) = vb;

    // ---- warp min/max of x ----
    float mx = fmaxf(fmaxf(fmaxf(va.x, va.y), fmaxf(va.z, va.w)),
                     fmaxf(fmaxf(vb.x, vb.y), fmaxf(vb.z, vb.w)));
    float mn = fminf(fminf(fminf(va.x, va.y), fminf(va.z, va.w)),
                     fminf(fminf(vb.x, vb.y), fminf(vb.z, vb.w)));
    #pragma unroll
    for (int o = 16; o; o >>= 1) {
        mx = fmaxf(mx, __shfl_xor_sync(0xffffffffu, mx, o));
        mn = fminf(mn, __shfl_xor_sync(0xffffffffu, mn, o));
    }

    // ---- minimal prologue gating the grid loop: A, C only (vector weight loads) ----
    const float4 ew = *(const float4*)emb_w;   // w
    const float4 eb = *(const float4*)emb_b;   // bias
    const float4 qb4 = *(const float4*)q_b;
    const float* qbp = (const float*)&qb4;

    float A = 0.f, C = 0.f;
    #pragma unroll
    for (int e = 0; e < 4; ++e) {
        const float4 qw = ((const float4*)q_w)[e];
        const float4 kw = ((const float4*)k_w)[e];
        const float qa = qw.x*ew.x + qw.y*ew.y + qw.z*ew.z + qw.w*ew.w;
        const float qc = qw.x*eb.x + qw.y*eb.y + qw.z*eb.z + qw.w*eb.w + qbp[e];
        const float ka = kw.x*ew.x + kw.y*ew.y + kw.z*ew.z + kw.w*ew.w;
        A = fmaf(qa, ka, A);
        C = fmaf(qc, ka, C);
    }
    A *= 0.5f;   // 1/sqrt(d), d=4
    C *= 0.5f;

    // ---- alpha grid (warp-uniform) ----
    const float LOG2E = 1.4426950408889634f;
    const float alo = (A >= 0.f) ? fmaf(A, mn, C) : fmaf(A, mx, C);
    const float ahi = (A >= 0.f) ? fmaf(A, mx, C) : fmaf(A, mn, C);
    const float hstep = fmaxf((ahi - alo) * (1.0f / (float)(GN - 1)), 1e-30f);

    __syncwarp(0xffffffffu);   // x slab visible to whole warp

    // ---- grid phase: node g = lane/4, quarter qd = lane&3, 64 j's per lane ----
    const int g  = lane >> 2;
    const int qd = lane & 3;
    const float ag2 = fmaf((float)g, hstep, alo) * LOG2E;
    const float mg  = fmaxf(ag2 * mx, ag2 * mn);   // max achieved by data

    const float4* xp = (const float4*)(xw + qd * RSTRIDE);

    float s0a = 0.f, s1a = 0.f, s2a = 0.f;
    float s0b = 0.f, s1b = 0.f, s2b = 0.f;
    #pragma unroll 4
    for (int c = 0; c < 16; c += 2) {
        const float4 v = xp[c];
        const float4 u = xp[c + 1];
        float p, px;
        p = ex2f(fmaf(ag2, v.x, -mg)); px = p*v.x; s0a += p; s1a += px; s2a = fmaf(px, v.x, s2a);
        p = ex2f(fmaf(ag2, v.y, -mg)); px = p*v.y; s0a += p; s1a += px; s2a = fmaf(px, v.y, s2a);
        p = ex2f(fmaf(ag2, v.z, -mg)); px = p*v.z; s0a += p; s1a += px; s2a = fmaf(px, v.z, s2a);
        p = ex2f(fmaf(ag2, v.w, -mg)); px = p*v.w; s0a += p; s1a += px; s2a = fmaf(px, v.w, s2a);
        p = ex2f(fmaf(ag2, u.x, -mg)); px = p*u.x; s0b += p; s1b += px; s2b = fmaf(px, u.x, s2b);
        p = ex2f(fmaf(ag2, u.y, -mg)); px = p*u.y; s0b += p; s1b += px; s2b = fmaf(px, u.y, s2b);
        p = ex2f(fmaf(ag2, u.z, -mg)); px = p*u.z; s0b += p; s1b += px; s2b = fmaf(px, u.z, s2b);
        p = ex2f(fmaf(ag2, u.w, -mg)); px = p*u.w; s0b += p; s1b += px; s2b = fmaf(px, u.w, s2b);
    }
    float s0 = s0a + s0b, s1 = s1a + s1b, s2 = s2a + s2b;
    #pragma unroll
    for (int o = 1; o < 4; o <<= 1) {
        s0 += __shfl_xor_sync(0xffffffffu, s0, o);
        s1 += __shfl_xor_sync(0xffffffffu, s1, o);
        s2 += __shfl_xor_sync(0xffffffffu, s2, o);
    }

    const float inv = __fdividef(1.0f, s0);
    const float mv  = s1 * inv;                          // m(alpha_g), node g in lanes 4g..4g+3
    const float dvh = fmaf(-mv, mv, s2 * inv) * hstep;   // h * m'(alpha_g)

    // ---- Hermite interpolation at this lane's 8 x values; nodes via shfl.idx ----
    const float inv_h = __fdividef(1.0f, hstep);
    const float xr[8] = {va.x, va.y, va.z, va.w, vb.x, vb.y, vb.z, vb.w};
    float psum = 0.f;
    #pragma unroll
    for (int k = 0; k < 8; ++k) {
        const float u  = (fmaf(A, xr[k], C) - alo) * inv_h;
        int g0 = (int)u;
        g0 = max(0, min(g0, GN - 2));
        const float tt = u - (float)g0;
        const int src = g0 << 2;
        const float m0 = __shfl_sync(0xffffffffu, mv,  src);
        const float m1 = __shfl_sync(0xffffffffu, mv,  src + 4);
        const float d0 = __shfl_sync(0xffffffffu, dvh, src);
        const float d1 = __shfl_sync(0xffffffffu, dvh, src + 4);
        const float t2 = tt * tt, t3 = t2 * tt;
        psum += (2.f*t3 - 3.f*t2 + 1.f) * m0
              + (t3 - 2.f*t2 + tt)      * d0
              + (-2.f*t3 + 3.f*t2)      * m1
              + (t3 - t2)               * d1;
    }
    #pragma unroll
    for (int o = 16; o; o >>= 1) psum += __shfl_xor_sync(0xffffffffu, psum, o);
    const float M = psum * (1.0f / (float)S_LEN);

    // ---- deferred uniform epilogue: V fold + folded MLP (lanes 0..7) ----
    const float F2B = f2_b[0];
    float yv = 0.f;
    if (lane < 8) {
        float vaw[4], vcw[4];
        const float4 vb4 = *(const float4*)v_b;
        const float* vbp = (const float*)&vb4;
        #pragma unroll
        for (int e = 0; e < 4; ++e) {
            const float4 vw = ((const float4*)v_w)[e];
            vaw[e] = vw.x*ew.x + vw.y*ew.y + vw.z*ew.z + vw.w*ew.w;
            vcw[e] = vw.x*eb.x + vw.y*eb.y + vw.z*eb.z + vw.w*eb.w + vbp[e];
        }
        const float4 f1 = ((const float4*)f1_w)[lane];
        const float P = f1.x*vaw[0] + f1.y*vaw[1] + f1.z*vaw[2] + f1.w*vaw[3];
        const float R = f1.x*vcw[0] + f1.y*vcw[1] + f1.z*vcw[2] + f1.w*vcw[3] + f1_b[lane];
        const float F = f2_w[lane];
        yv = F * fmaxf(fmaf(P, M, R), 0.f);
    }
    yv += __shfl_xor_sync(0xffffffffu, yv, 1);
    yv += __shfl_xor_sync(0xffffffffu, yv, 2);
    yv += __shfl_xor_sync(0xffffffffu, yv, 4);
    if (lane == 0) out[b] = yv + F2B;
}

extern "C" void kernel_launch(void* const* d_in, const int* in_sizes, int n_in,
                              void* d_out, int out_size) {
    const float* x     = (const float*)d_in[0];
    const float* emb_w = (const float*)d_in[1];
    const float* emb_b = (const float*)d_in[2];
    const float* q_w   = (const float*)d_in[3];
    const float* q_b   = (const float*)d_in[4];
    const float* k_w   = (const float*)d_in[5];
    const float* k_b   = (const float*)d_in[6];
    const float* v_w   = (const float*)d_in[7];
    const float* v_b   = (const float*)d_in[8];
    const float* f1_w  = (const float*)d_in[9];
    const float* f1_b  = (const float*)d_in[10];
    const float* f2_w  = (const float*)d_in[11];
    const float* f2_b  = (const float*)d_in[12];

    const int B = in_sizes[0] / S_LEN;

    pico_transformer_adder_kernel<<<B, THREADS>>>(
        x, emb_w, emb_b, q_w, q_b, k_w, k_b, v_w, v_b,
        f1_w, f1_b, f2_w, f2_b, (float*)d_out);
}

// round 11
// speedup vs baseline: 1.0625x; 1.0625x over previous
#include <cuda_runtime.h>

#define S_LEN 256
#define GN 8                   // interpolation grid nodes
#define THREADS 32             // one warp = one batch per block
#define RSTRIDE 68             // floats per quarter-region (64 + 4 pad)

__device__ __forceinline__ float ex2f(float v) {
    float y;
    asm("ex2.approx.ftz.f32 %0, %1;" : "=f"(y) : "f"(v));
    return y;
}

__global__ void __launch_bounds__(THREADS)
pico_transformer_adder_kernel(
    const float* __restrict__ x,
    const float* __restrict__ emb_w,
    const float* __restrict__ emb_b,
    const float* __restrict__ q_w,
    const float* __restrict__ q_b,
    const float* __restrict__ k_w,
    const float* __restrict__ k_b,
    const float* __restrict__ v_w,
    const float* __restrict__ v_b,
    const float* __restrict__ f1_w,
    const float* __restrict__ f1_b,
    const float* __restrict__ f2_w,
    const float* __restrict__ f2_b,
    float* __restrict__ out)
{
    __shared__ __align__(16) float xw[4 * RSTRIDE];   // x values only

    const int lane = threadIdx.x;
    const int l8   = lane & 7;
    const int b    = blockIdx.x;

    // ================= FRONT-BATCHED LOADS: everything the kernel will ever
    // read from global memory is issued here, so all LDG latency overlaps the
    // min/max + grid phase instead of being exposed on the tail. =============
    const float4* xr4 = (const float4*)(x + b * S_LEN);
    const float4 va = xr4[lane * 2];
    const float4 vb = xr4[lane * 2 + 1];

    const float4 ew  = *(const float4*)emb_w;
    const float4 eb  = *(const float4*)emb_b;
    const float4 qb4 = *(const float4*)q_b;
    const float4 vb4 = *(const float4*)v_b;
    float4 qw[4], kw[4], vw[4];
    #pragma unroll
    for (int e = 0; e < 4; ++e) {
        qw[e] = ((const float4*)q_w)[e];
        kw[e] = ((const float4*)k_w)[e];
        vw[e] = ((const float4*)v_w)[e];
    }
    const float4 f1  = ((const float4*)f1_w)[l8];   // row lane&7 (unconditional)
    const float  f1b = f1_b[l8];
    const float  F   = f2_w[l8];
    const float  F2B = f2_b[0];

    // ---- stage x into slab: quarter r = lane>>3 at r*RSTRIDE ----
    const int base = (lane >> 3) * RSTRIDE + l8 * 8;
    *(float4*)(xw + base)     = va;
    *(float4*)(xw + base + 4) = vb;

    // ---- warp min/max of x ----
    float mx = fmaxf(fmaxf(fmaxf(va.x, va.y), fmaxf(va.z, va.w)),
                     fmaxf(fmaxf(vb.x, vb.y), fmaxf(vb.z, vb.w)));
    float mn = fminf(fminf(fminf(va.x, va.y), fminf(va.z, va.w)),
                     fminf(fminf(vb.x, vb.y), fminf(vb.z, vb.w)));
    #pragma unroll
    for (int o = 16; o; o >>= 1) {
        mx = fmaxf(mx, __shfl_xor_sync(0xffffffffu, mx, o));
        mn = fminf(mn, __shfl_xor_sync(0xffffffffu, mn, o));
    }

    // ---- A, C (gates the grid loop) ----
    const float* qbp = (const float*)&qb4;
    float A = 0.f, C = 0.f;
    #pragma unroll
    for (int e = 0; e < 4; ++e) {
        const float qa = qw[e].x*ew.x + qw[e].y*ew.y + qw[e].z*ew.z + qw[e].w*ew.w;
        const float qc = qw[e].x*eb.x + qw[e].y*eb.y + qw[e].z*eb.z + qw[e].w*eb.w + qbp[e];
        const float ka = kw[e].x*ew.x + kw[e].y*ew.y + kw[e].z*ew.z + kw[e].w*ew.w;
        A = fmaf(qa, ka, A);
        C = fmaf(qc, ka, C);
    }
    A *= 0.5f;   // 1/sqrt(d), d=4
    C *= 0.5f;

    // ---- alpha grid (warp-uniform) ----
    const float LOG2E = 1.4426950408889634f;
    const float alo = (A >= 0.f) ? fmaf(A, mn, C) : fmaf(A, mx, C);
    const float ahi = (A >= 0.f) ? fmaf(A, mx, C) : fmaf(A, mn, C);
    const float hstep = fmaxf((ahi - alo) * (1.0f / (float)(GN - 1)), 1e-30f);

    __syncwarp(0xffffffffu);   // x slab visible to whole warp

    // ---- grid phase: node g = lane/4, quarter qd = lane&3, 64 j's per lane ----
    const int g  = lane >> 2;
    const int qd = lane & 3;
    const float ag2 = fmaf((float)g, hstep, alo) * LOG2E;
    const float mg  = fmaxf(ag2 * mx, ag2 * mn);   // max achieved by data

    const float4* xp = (const float4*)(xw + qd * RSTRIDE);

    float s0a = 0.f, s1a = 0.f, s2a = 0.f;
    float s0b = 0.f, s1b = 0.f, s2b = 0.f;
    #pragma unroll 4
    for (int c = 0; c < 16; c += 2) {
        const float4 v = xp[c];
        const float4 u = xp[c + 1];
        float p, px;
        p = ex2f(fmaf(ag2, v.x, -mg)); px = p*v.x; s0a += p; s1a += px; s2a = fmaf(px, v.x, s2a);
        p = ex2f(fmaf(ag2, v.y, -mg)); px = p*v.y; s0a += p; s1a += px; s2a = fmaf(px, v.y, s2a);
        p = ex2f(fmaf(ag2, v.z, -mg)); px = p*v.z; s0a += p; s1a += px; s2a = fmaf(px, v.z, s2a);
        p = ex2f(fmaf(ag2, v.w, -mg)); px = p*v.w; s0a += p; s1a += px; s2a = fmaf(px, v.w, s2a);
        p = ex2f(fmaf(ag2, u.x, -mg)); px = p*u.x; s0b += p; s1b += px; s2b = fmaf(px, u.x, s2b);
        p = ex2f(fmaf(ag2, u.y, -mg)); px = p*u.y; s0b += p; s1b += px; s2b = fmaf(px, u.y, s2b);
        p = ex2f(fmaf(ag2, u.z, -mg)); px = p*u.z; s0b += p; s1b += px; s2b = fmaf(px, u.z, s2b);
        p = ex2f(fmaf(ag2, u.w, -mg)); px = p*u.w; s0b += p; s1b += px; s2b = fmaf(px, u.w, s2b);
    }
    float s0 = s0a + s0b, s1 = s1a + s1b, s2 = s2a + s2b;
    #pragma unroll
    for (int o = 1; o < 4; o <<= 1) {
        s0 += __shfl_xor_sync(0xffffffffu, s0, o);
        s1 += __shfl_xor_sync(0xffffffffu, s1, o);
        s2 += __shfl_xor_sync(0xffffffffu, s2, o);
    }

    const float inv = __fdividef(1.0f, s0);
    const float mv  = s1 * inv;                          // m(alpha_g), node g in lanes 4g..4g+3
    const float dvh = fmaf(-mv, mv, s2 * inv) * hstep;   // h * m'(alpha_g)

    // ---- Hermite interpolation at this lane's 8 x values; nodes via shfl.idx ----
    const float inv_h = __fdividef(1.0f, hstep);
    const float xr[8] = {va.x, va.y, va.z, va.w, vb.x, vb.y, vb.z, vb.w};
    float psum = 0.f;
    #pragma unroll
    for (int k = 0; k < 8; ++k) {
        const float u  = (fmaf(A, xr[k], C) - alo) * inv_h;
        int g0 = (int)u;
        g0 = max(0, min(g0, GN - 2));
        const float tt = u - (float)g0;
        const int src = g0 << 2;
        const float m0 = __shfl_sync(0xffffffffu, mv,  src);
        const float m1 = __shfl_sync(0xffffffffu, mv,  src + 4);
        const float d0 = __shfl_sync(0xffffffffu, dvh, src);
        const float d1 = __shfl_sync(0xffffffffu, dvh, src + 4);
        const float t2 = tt * tt, t3 = t2 * tt;
        psum += (2.f*t3 - 3.f*t2 + 1.f) * m0
              + (t3 - 2.f*t2 + tt)      * d0
              + (-2.f*t3 + 3.f*t2)      * m1
              + (t3 - t2)               * d1;
    }
    #pragma unroll
    for (int o = 16; o; o >>= 1) psum += __shfl_xor_sync(0xffffffffu, psum, o);
    const float M = psum * (1.0f / (float)S_LEN);

    // ---- epilogue: all data already register-resident; pure FMA ----
    float yv = 0.f;
    if (lane < 8) {
        const float* vbp = (const float*)&vb4;
        float vaw[4], vcw[4];
        #pragma unroll
        for (int e = 0; e < 4; ++e) {
            vaw[e] = vw[e].x*ew.x + vw[e].y*ew.y + vw[e].z*ew.z + vw[e].w*ew.w;
            vcw[e] = vw[e].x*eb.x + vw[e].y*eb.y + vw[e].z*eb.z + vw[e].w*eb.w + vbp[e];
        }
        const float P = f1.x*vaw[0] + f1.y*vaw[1] + f1.z*vaw[2] + f1.w*vaw[3];
        const float R = f1.x*vcw[0] + f1.y*vcw[1] + f1.z*vcw[2] + f1.w*vcw[3] + f1b;
        yv = F * fmaxf(fmaf(P, M, R), 0.f);
    }
    yv += __shfl_xor_sync(0xffffffffu, yv, 1);
    yv += __shfl_xor_sync(0xffffffffu, yv, 2);
    yv += __shfl_xor_sync(0xffffffffu, yv, 4);
    if (lane == 0) out[b] = yv + F2B;
}

extern "C" void kernel_launch(void* const* d_in, const int* in_sizes, int n_in,
                              void* d_out, int out_size) {
    const float* x     = (const float*)d_in[0];
    const float* emb_w = (const float*)d_in[1];
    const float* emb_b = (const float*)d_in[2];
    const float* q_w   = (const float*)d_in[3];
    const float* q_b   = (const float*)d_in[4];
    const float* k_w   = (const float*)d_in[5];
    const float* k_b   = (const float*)d_in[6];
    const float* v_w   = (const float*)d_in[7];
    const float* v_b   = (const float*)d_in[8];
    const float* f1_w  = (const float*)d_in[9];
    const float* f1_b  = (const float*)d_in[10];
    const float* f2_w  = (const float*)d_in[11];
    const float* f2_b  = (const float*)d_in[12];

    const int B = in_sizes[0] / S_LEN;

    pico_transformer_adder_kernel<<<B, THREADS>>>(
        x, emb_w, emb_b, q_w, q_b, k_w, k_b, v_w, v_b,
        f1_w, f1_b, f2_w, f2_b, (float*)d_out);
}

// round 12
// speedup vs baseline: 1.0676x; 1.0048x over previous
#include <cuda_runtime.h>

#define S_LEN 256
#define GN 8                   // interpolation grid nodes
#define THREADS 32             // one warp = one batch per block
#define RSTRIDE 68             // floats per quarter-region (64 + 4 pad)

typedef unsigned long long ull;

__device__ __forceinline__ float ex2f(float v) {
    float y;
    asm("ex2.approx.ftz.f32 %0, %1;" : "=f"(y) : "f"(v));
    return y;
}
__device__ __forceinline__ ull pack2(float lo, float hi) {
    ull r; asm("mov.b64 %0, {%1, %2};" : "=l"(r) : "f"(lo), "f"(hi)); return r;
}
__device__ __forceinline__ void unpack2(ull v, float& lo, float& hi) {
    asm("mov.b64 {%0, %1}, %2;" : "=f"(lo), "=f"(hi) : "l"(v));
}
__device__ __forceinline__ ull fma2(ull a, ull b, ull c) {
    ull d; asm("fma.rn.f32x2 %0, %1, %2, %3;" : "=l"(d) : "l"(a), "l"(b), "l"(c)); return d;
}
__device__ __forceinline__ ull add2(ull a, ull b) {
    ull d; asm("add.rn.f32x2 %0, %1, %2;" : "=l"(d) : "l"(a), "l"(b)); return d;
}
__device__ __forceinline__ ull mul2(ull a, ull b) {
    ull d; asm("mul.rn.f32x2 %0, %1, %2;" : "=l"(d) : "l"(a), "l"(b)); return d;
}

// Accumulate one float4 (2 packed pairs) of tilted-softmax sums.
__device__ __forceinline__ void acc4(const float4 v, const ull AG2, const ull NMG,
                                     ull& S0, ull& S1, ull& S2) {
    const ull X0 = pack2(v.x, v.y);
    const ull X1 = pack2(v.z, v.w);
    float t0, t1, t2, t3;
    unpack2(fma2(AG2, X0, NMG), t0, t1);
    unpack2(fma2(AG2, X1, NMG), t2, t3);
    const ull P0  = pack2(ex2f(t0), ex2f(t1));
    const ull P1  = pack2(ex2f(t2), ex2f(t3));
    const ull PX0 = mul2(P0, X0);
    const ull PX1 = mul2(P1, X1);
    S0 = add2(S0, add2(P0, P1));
    S1 = add2(S1, add2(PX0, PX1));
    S2 = fma2(PX0, X0, fma2(PX1, X1, S2));
}

__global__ void __launch_bounds__(THREADS)
pico_transformer_adder_kernel(
    const float* __restrict__ x,
    const float* __restrict__ emb_w,
    const float* __restrict__ emb_b,
    const float* __restrict__ q_w,
    const float* __restrict__ q_b,
    const float* __restrict__ k_w,
    const float* __restrict__ k_b,
    const float* __restrict__ v_w,
    const float* __restrict__ v_b,
    const float* __restrict__ f1_w,
    const float* __restrict__ f1_b,
    const float* __restrict__ f2_w,
    const float* __restrict__ f2_b,
    float* __restrict__ out)
{
    __shared__ __align__(16) float xw[4 * RSTRIDE];   // x values only

    const int lane = threadIdx.x;
    const int l8   = lane & 7;
    const int b    = blockIdx.x;

    // ---- FRONT-BATCHED LOADS: all global reads issued here (round-11 win) ----
    const float4* xr4 = (const float4*)(x + b * S_LEN);
    const float4 va = xr4[lane * 2];
    const float4 vb = xr4[lane * 2 + 1];

    const float4 ew  = *(const float4*)emb_w;
    const float4 eb  = *(const float4*)emb_b;
    const float4 qb4 = *(const float4*)q_b;
    const float4 vb4 = *(const float4*)v_b;
    float4 qw[4], kw[4], vw[4];
    #pragma unroll
    for (int e = 0; e < 4; ++e) {
        qw[e] = ((const float4*)q_w)[e];
        kw[e] = ((const float4*)k_w)[e];
        vw[e] = ((const float4*)v_w)[e];
    }
    const float4 f1  = ((const float4*)f1_w)[l8];
    const float  f1b = f1_b[l8];
    const float  F   = f2_w[l8];
    const float  F2B = f2_b[0];

    // ---- stage x into slab: quarter r = lane>>3 at r*RSTRIDE ----
    const int base = (lane >> 3) * RSTRIDE + l8 * 8;
    *(float4*)(xw + base)     = va;
    *(float4*)(xw + base + 4) = vb;

    // ---- warp min/max of x ----
    float mx = fmaxf(fmaxf(fmaxf(va.x, va.y), fmaxf(va.z, va.w)),
                     fmaxf(fmaxf(vb.x, vb.y), fmaxf(vb.z, vb.w)));
    float mn = fminf(fminf(fminf(va.x, va.y), fminf(va.z, va.w)),
                     fminf(fminf(vb.x, vb.y), fminf(vb.z, vb.w)));
    #pragma unroll
    for (int o = 16; o; o >>= 1) {
        mx = fmaxf(mx, __shfl_xor_sync(0xffffffffu, mx, o));
        mn = fminf(mn, __shfl_xor_sync(0xffffffffu, mn, o));
    }

    // ---- A, C (gates the grid loop) ----
    const float* qbp = (const float*)&qb4;
    float A = 0.f, C = 0.f;
    #pragma unroll
    for (int e = 0; e < 4; ++e) {
        const float qa = qw[e].x*ew.x + qw[e].y*ew.y + qw[e].z*ew.z + qw[e].w*ew.w;
        const float qc = qw[e].x*eb.x + qw[e].y*eb.y + qw[e].z*eb.z + qw[e].w*eb.w + qbp[e];
        const float ka = kw[e].x*ew.x + kw[e].y*ew.y + kw[e].z*ew.z + kw[e].w*ew.w;
        A = fmaf(qa, ka, A);
        C = fmaf(qc, ka, C);
    }
    A *= 0.5f;   // 1/sqrt(d), d=4
    C *= 0.5f;

    // ---- alpha grid (warp-uniform) ----
    const float LOG2E = 1.4426950408889634f;
    const float alo = (A >= 0.f) ? fmaf(A, mn, C) : fmaf(A, mx, C);
    const float ahi = (A >= 0.f) ? fmaf(A, mx, C) : fmaf(A, mn, C);
    const float hstep = fmaxf((ahi - alo) * (1.0f / (float)(GN - 1)), 1e-30f);

    __syncwarp(0xffffffffu);   // x slab visible to whole warp

    // ---- grid phase: node g = lane/4, quarter qd = lane&3, 64 j's per lane ----
    const int g  = lane >> 2;
    const int qd = lane & 3;
    const float ag2 = fmaf((float)g, hstep, alo) * LOG2E;
    const float mg  = fmaxf(ag2 * mx, ag2 * mn);   // max achieved by data

    const ull AG2 = pack2(ag2, ag2);
    const ull NMG = pack2(-mg, -mg);

    const float4* xp = (const float4*)(xw + qd * RSTRIDE);

    ull S0a = 0ull, S1a = 0ull, S2a = 0ull;
    ull S0b = 0ull, S1b = 0ull, S2b = 0ull;
    #pragma unroll 4
    for (int c = 0; c < 16; c += 2) {
        acc4(xp[c],     AG2, NMG, S0a, S1a, S2a);
        acc4(xp[c + 1], AG2, NMG, S0b, S1b, S2b);
    }
    float s0, s1, s2;
    {
        float lo, hi;
        unpack2(add2(S0a, S0b), lo, hi); s0 = lo + hi;
        unpack2(add2(S1a, S1b), lo, hi); s1 = lo + hi;
        unpack2(add2(S2a, S2b), lo, hi); s2 = lo + hi;
    }
    #pragma unroll
    for (int o = 1; o < 4; o <<= 1) {
        s0 += __shfl_xor_sync(0xffffffffu, s0, o);
        s1 += __shfl_xor_sync(0xffffffffu, s1, o);
        s2 += __shfl_xor_sync(0xffffffffu, s2, o);
    }

    const float inv = __fdividef(1.0f, s0);
    const float mv  = s1 * inv;                          // m(alpha_g), node g in lanes 4g..4g+3
    const float dvh = fmaf(-mv, mv, s2 * inv) * hstep;   // h * m'(alpha_g)

    // ---- Hermite interpolation at this lane's 8 x values; nodes via shfl.idx ----
    const float inv_h = __fdividef(1.0f, hstep);
    const float xr[8] = {va.x, va.y, va.z, va.w, vb.x, vb.y, vb.z, vb.w};
    float psum = 0.f;
    #pragma unroll
    for (int k = 0; k < 8; ++k) {
        const float u  = (fmaf(A, xr[k], C) - alo) * inv_h;
        int g0 = (int)u;
        g0 = max(0, min(g0, GN - 2));
        const float tt = u - (float)g0;
        const int src = g0 << 2;
        const float m0 = __shfl_sync(0xffffffffu, mv,  src);
        const float m1 = __shfl_sync(0xffffffffu, mv,  src + 4);
        const float d0 = __shfl_sync(0xffffffffu, dvh, src);
        const float d1 = __shfl_sync(0xffffffffu, dvh, src + 4);
        const float t2 = tt * tt, t3 = t2 * tt;
        psum += (2.f*t3 - 3.f*t2 + 1.f) * m0
              + (t3 - 2.f*t2 + tt)      * d0
              + (-2.f*t3 + 3.f*t2)      * m1
              + (t3 - t2)               * d1;
    }
    #pragma unroll
    for (int o = 16; o; o >>= 1) psum += __shfl_xor_sync(0xffffffffu, psum, o);
    const float M = psum * (1.0f / (float)S_LEN);

    // ---- epilogue: all data register-resident; pure FMA ----
    float yv = 0.f;
    if (lane < 8) {
        const float* vbp = (const float*)&vb4;
        float vaw[4], vcw[4];
        #pragma unroll
        for (int e = 0; e < 4; ++e) {
            vaw[e] = vw[e].x*ew.x + vw[e].y*ew.y + vw[e].z*ew.z + vw[e].w*ew.w;
            vcw[e] = vw[e].x*eb.x + vw[e].y*eb.y + vw[e].z*eb.z + vw[e].w*eb.w + vbp[e];
        }
        const float P = f1.x*vaw[0] + f1.y*vaw[1] + f1.z*vaw[2] + f1.w*vaw[3];
        const float R = f1.x*vcw[0] + f1.y*vcw[1] + f1.z*vcw[2] + f1.w*vcw[3] + f1b;
        yv = F * fmaxf(fmaf(P, M, R), 0.f);
    }
    yv += __shfl_xor_sync(0xffffffffu, yv, 1);
    yv += __shfl_xor_sync(0xffffffffu, yv, 2);
    yv += __shfl_xor_sync(0xffffffffu, yv, 4);
    if (lane == 0) out[b] = yv + F2B;
}

extern "C" void kernel_launch(void* const* d_in, const int* in_sizes, int n_in,
                              void* d_out, int out_size) {
    const float* x     = (const float*)d_in[0];
    const float* emb_w = (const float*)d_in[1];
    const float* emb_b = (const float*)d_in[2];
    const float* q_w   = (const float*)d_in[3];
    const float* q_b   = (const float*)d_in[4];
    const float* k_w   = (const float*)d_in[5];
    const float* k_b   = (const float*)d_in[6];
    const float* v_w   = (const float*)d_in[7];
    const float* v_b   = (const float*)d_in[8];
    const float* f1_w  = (const float*)d_in[9];
    const float* f1_b  = (const float*)d_in[10];
    const float* f2_w  = (const float*)d_in[11];
    const float* f2_b  = (const float*)d_in[12];

    const int B = in_sizes[0] / S_LEN;

    pico_transformer_adder_kernel<<<B, THREADS>>>(
        x, emb_w, emb_b, q_w, q_b, k_w, k_b, v_w, v_b,
        f1_w, f1_b, f2_w, f2_b, (float*)d_out);
}